// round 1
// baseline (speedup 1.0000x reference)
#include <cuda_runtime.h>
#include <cstdint>

#define BB 2
#define NN 8192
#define MM 8192
#define NSPLIT 8
#define TILE 256
#define BLK 256

// Scratch (device globals; no allocations allowed)
__device__ unsigned long long g_closest[BB * MM];  // packed (d2_bits<<32)|idx, argmin over N for each ref m
__device__ unsigned int       g_minxy[BB * NN];    // d2 bits, min over M for each pred n

__global__ void init_kernel() {
    int i = blockIdx.x * blockDim.x + threadIdx.x;
    if (i < BB * MM) g_closest[i] = 0xFFFFFFFFFFFFFFFFull;
    if (i < BB * NN) g_minxy[i] = 0x7F800000u;  // +inf
}

// For each ref point m: min+argmin of d2 over a chunk of pred points (axis=1 argmin).
__global__ void yx_kernel(const float* __restrict__ pred_pts,
                          const float* __restrict__ ref_pts) {
    __shared__ __align__(16) float s[TILE * 3];
    const int b = blockIdx.z;
    const int m = blockIdx.x * BLK + threadIdx.x;
    const int chunk = NN / NSPLIT;
    const int n0base = blockIdx.y * chunk;

    const float* rp = ref_pts + ((size_t)b * MM + m) * 3;
    const float rx = rp[0], ry = rp[1], rz = rp[2];

    float bestd = 3.402823466e38f;
    int besti = 0;

    const float* pbase = pred_pts + ((size_t)b * NN + n0base) * 3;

    for (int t0 = 0; t0 < chunk; t0 += TILE) {
        __syncthreads();
        const float* src = pbase + (size_t)t0 * 3;
        #pragma unroll
        for (int i = threadIdx.x; i < TILE * 3; i += BLK) s[i] = src[i];
        __syncthreads();

        #pragma unroll 8
        for (int j = 0; j < TILE; j += 4) {
            const float4 v0 = *(const float4*)&s[3 * j + 0];
            const float4 v1 = *(const float4*)&s[3 * j + 4];
            const float4 v2 = *(const float4*)&s[3 * j + 8];
            float dx, dy, dz, d2;
            // point j+0
            dx = v0.x - rx; dy = v0.y - ry; dz = v0.z - rz;
            d2 = fmaf(dz, dz, fmaf(dy, dy, dx * dx));
            if (d2 < bestd) { bestd = d2; besti = n0base + t0 + j + 0; }
            // point j+1
            dx = v0.w - rx; dy = v1.x - ry; dz = v1.y - rz;
            d2 = fmaf(dz, dz, fmaf(dy, dy, dx * dx));
            if (d2 < bestd) { bestd = d2; besti = n0base + t0 + j + 1; }
            // point j+2
            dx = v1.z - rx; dy = v1.w - ry; dz = v2.x - rz;
            d2 = fmaf(dz, dz, fmaf(dy, dy, dx * dx));
            if (d2 < bestd) { bestd = d2; besti = n0base + t0 + j + 2; }
            // point j+3
            dx = v2.y - rx; dy = v2.z - ry; dz = v2.w - rz;
            d2 = fmaf(dz, dz, fmaf(dy, dy, dx * dx));
            if (d2 < bestd) { bestd = d2; besti = n0base + t0 + j + 3; }
        }
    }

    const unsigned long long packed =
        ((unsigned long long)__float_as_uint(bestd) << 32) | (unsigned)besti;
    atomicMin(&g_closest[b * MM + m], packed);
}

// For each pred point n: min of d2 over a chunk of ref points (axis=2 min).
__global__ void xy_kernel(const float* __restrict__ pred_pts,
                          const float* __restrict__ ref_pts) {
    __shared__ __align__(16) float s[TILE * 3];
    const int b = blockIdx.z;
    const int n = blockIdx.x * BLK + threadIdx.x;
    const int chunk = MM / NSPLIT;
    const int m0base = blockIdx.y * chunk;

    const float* pp = pred_pts + ((size_t)b * NN + n) * 3;
    const float px = pp[0], py = pp[1], pz = pp[2];

    float bestd = 3.402823466e38f;

    const float* rbase = ref_pts + ((size_t)b * MM + m0base) * 3;

    for (int t0 = 0; t0 < chunk; t0 += TILE) {
        __syncthreads();
        const float* src = rbase + (size_t)t0 * 3;
        #pragma unroll
        for (int i = threadIdx.x; i < TILE * 3; i += BLK) s[i] = src[i];
        __syncthreads();

        #pragma unroll 8
        for (int j = 0; j < TILE; j += 4) {
            const float4 v0 = *(const float4*)&s[3 * j + 0];
            const float4 v1 = *(const float4*)&s[3 * j + 4];
            const float4 v2 = *(const float4*)&s[3 * j + 8];
            float dx, dy, dz, d2;
            dx = v0.x - px; dy = v0.y - py; dz = v0.z - pz;
            d2 = fmaf(dz, dz, fmaf(dy, dy, dx * dx));
            bestd = fminf(bestd, d2);
            dx = v0.w - px; dy = v1.x - py; dz = v1.y - pz;
            d2 = fmaf(dz, dz, fmaf(dy, dy, dx * dx));
            bestd = fminf(bestd, d2);
            dx = v1.z - px; dy = v1.w - py; dz = v2.x - pz;
            d2 = fmaf(dz, dz, fmaf(dy, dy, dx * dx));
            bestd = fminf(bestd, d2);
            dx = v2.y - px; dy = v2.z - py; dz = v2.w - pz;
            d2 = fmaf(dz, dz, fmaf(dy, dy, dx * dx));
            bestd = fminf(bestd, d2);
        }
    }

    atomicMin(&g_minxy[b * NN + n], __float_as_uint(bestd));
}

// Single-block deterministic finalization: gather sdf/color at argmin index,
// reduce all sums in double, emit [sdf_l1, color_l1, chamfer].
__global__ void final_kernel(const float* __restrict__ pred_sdfs,
                             const float* __restrict__ pred_cols,
                             const float* __restrict__ ref_sdfs,
                             const float* __restrict__ ref_cols,
                             float* __restrict__ out) {
    __shared__ double red[1024];
    double s_sdf = 0.0, s_col = 0.0, s_yx = 0.0, s_xy = 0.0;

    for (int i = threadIdx.x; i < BB * MM; i += blockDim.x) {
        const unsigned long long p = g_closest[i];
        const unsigned idx = (unsigned)(p & 0xFFFFFFFFu);
        const float d2 = __uint_as_float((unsigned)(p >> 32));
        s_yx += (double)d2;
        const int b = i / MM;
        s_sdf += (double)fabsf(ref_sdfs[(size_t)b * MM + idx] - pred_sdfs[i]);
        const float* pc = pred_cols + (size_t)i * 3;
        const float* rc = ref_cols + ((size_t)b * MM + idx) * 3;
        s_col += (double)(fabsf(rc[0] - pc[0]) + fabsf(rc[1] - pc[1]) + fabsf(rc[2] - pc[2]));
    }
    for (int i = threadIdx.x; i < BB * NN; i += blockDim.x) {
        s_xy += (double)__uint_as_float(g_minxy[i]);
    }

    // 4 sequential tree reductions (deterministic)
    double vals[4] = {s_sdf, s_col, s_yx, s_xy};
    double tot[4];
    for (int v = 0; v < 4; v++) {
        red[threadIdx.x] = vals[v];
        __syncthreads();
        for (int sft = 512; sft > 0; sft >>= 1) {
            if (threadIdx.x < sft) red[threadIdx.x] += red[threadIdx.x + sft];
            __syncthreads();
        }
        tot[v] = red[0];
        __syncthreads();
    }

    if (threadIdx.x == 0) {
        out[0] = (float)(tot[0] / (double)(BB * MM));
        out[1] = (float)(tot[1] / (double)(BB * MM * 3));
        out[2] = (float)(tot[3] / (double)(BB * NN) + tot[2] / (double)(BB * MM));
    }
}

extern "C" void kernel_launch(void* const* d_in, const int* in_sizes, int n_in,
                              void* d_out, int out_size) {
    const float* pred_pts  = (const float*)d_in[0];
    const float* pred_sdfs = (const float*)d_in[1];
    const float* pred_cols = (const float*)d_in[2];
    const float* ref_pts   = (const float*)d_in[3];
    const float* ref_sdfs  = (const float*)d_in[4];
    const float* ref_cols  = (const float*)d_in[5];
    float* out = (float*)d_out;

    init_kernel<<<(BB * MM + 255) / 256, 256>>>();
    yx_kernel<<<dim3(MM / BLK, NSPLIT, BB), BLK>>>(pred_pts, ref_pts);
    xy_kernel<<<dim3(NN / BLK, NSPLIT, BB), BLK>>>(pred_pts, ref_pts);
    final_kernel<<<1, 1024>>>(pred_sdfs, pred_cols, ref_sdfs, ref_cols, out);
}

// round 3
// speedup vs baseline: 1.9605x; 1.9605x over previous
#include <cuda_runtime.h>
#include <cstdint>

#define BB 2
#define NPTS 8192
#define BLK 256
#define QPT 2
#define NSPLIT 16
#define CHUNK (NPTS / NSPLIT)     // 512 candidates per block
#define GX (NPTS / (BLK * QPT))   // 16
#define PBLK 64

typedef unsigned long long ull;

// Scratch (device globals; no allocations allowed)
__device__ float g_px[BB*NPTS], g_py[BB*NPTS], g_pz[BB*NPTS], g_pc[BB*NPTS]; // pred: -2x,-2y,-2z,|p|^2
__device__ float g_rx[BB*NPTS], g_ry[BB*NPTS], g_rz[BB*NPTS], g_rc[BB*NPTS]; // ref:  -2x,-2y,-2z,|r|^2
__device__ ull      g_closest[BB*NPTS];   // packed (orderable_key<<32)|pred_idx per ref point
__device__ unsigned g_minxy[BB*NPTS];     // d2 bits (>=0) per pred point
__device__ double   g_part[PBLK*4];

__device__ __forceinline__ ull fma2(ull a, ull b, ull c){
    ull d; asm("fma.rn.f32x2 %0, %1, %2, %3;" : "=l"(d) : "l"(a), "l"(b), "l"(c)); return d;
}
__device__ __forceinline__ ull pk2(float x){
    ull v; asm("mov.b64 %0, {%1, %2};" : "=l"(v)
               : "r"(__float_as_uint(x)), "r"(__float_as_uint(x)));
    return v;
}
__device__ __forceinline__ void unpk(ull v, float& lo, float& hi){
    unsigned a, b;
    asm("mov.b64 {%0, %1}, %2;" : "=r"(a), "=r"(b) : "l"(v));
    lo = __uint_as_float(a); hi = __uint_as_float(b);
}
// Monotone float->uint key (handles negatives), injective both ways.
__device__ __forceinline__ unsigned fkey(float f){
    unsigned b = __float_as_uint(f);
    return b ^ ((unsigned)((int)b >> 31) | 0x80000000u);
}
__device__ __forceinline__ float funkey(unsigned u){
    unsigned b = u ^ ((u & 0x80000000u) ? 0x80000000u : 0xFFFFFFFFu);
    return __uint_as_float(b);
}

__global__ void prep_kernel(const float* __restrict__ pred_pts,
                            const float* __restrict__ ref_pts) {
    int i = blockIdx.x * blockDim.x + threadIdx.x;
    if (i >= BB * NPTS) return;
    float x = pred_pts[3*i], y = pred_pts[3*i+1], z = pred_pts[3*i+2];
    g_px[i] = -2.f*x; g_py[i] = -2.f*y; g_pz[i] = -2.f*z;
    g_pc[i] = x*x + y*y + z*z;
    x = ref_pts[3*i]; y = ref_pts[3*i+1]; z = ref_pts[3*i+2];
    g_rx[i] = -2.f*x; g_ry[i] = -2.f*y; g_rz[i] = -2.f*z;
    g_rc[i] = x*x + y*y + z*z;
    g_closest[i] = 0xFFFFFFFFFFFFFFFFull;
    g_minxy[i]   = 0x7F800000u;
}

// pred -> ref: min over ref (candidates = ref packed arrays), queries = pred points.
__global__ void xy_kernel(const float* __restrict__ pred_pts) {
    __shared__ __align__(16) float sx[CHUNK], sy[CHUNK], sz[CHUNK], sc[CHUNK];
    const int b  = blockIdx.z;
    const int c0 = blockIdx.y * CHUNK;
    const int n0 = blockIdx.x * (BLK * QPT) + threadIdx.x;
    const int base = b * NPTS + c0;

    ((float2*)sx)[threadIdx.x] = ((const float2*)(g_rx + base))[threadIdx.x];
    ((float2*)sy)[threadIdx.x] = ((const float2*)(g_ry + base))[threadIdx.x];
    ((float2*)sz)[threadIdx.x] = ((const float2*)(g_rz + base))[threadIdx.x];
    ((float2*)sc)[threadIdx.x] = ((const float2*)(g_rc + base))[threadIdx.x];

    const float* q0p = pred_pts + (size_t)(b*NPTS + n0) * 3;
    const float* q1p = pred_pts + (size_t)(b*NPTS + n0 + BLK) * 3;
    const float q0x = q0p[0], q0y = q0p[1], q0z = q0p[2];
    const float q1x = q1p[0], q1y = q1p[1], q1z = q1p[2];
    const ull q0xp = pk2(q0x), q0yp = pk2(q0y), q0zp = pk2(q0z);
    const ull q1xp = pk2(q1x), q1yp = pk2(q1y), q1zp = pk2(q1z);
    __syncthreads();

    const ull* sxu = (const ull*)sx; const ull* syu = (const ull*)sy;
    const ull* szu = (const ull*)sz; const ull* scu = (const ull*)sc;

    const float INFF = __int_as_float(0x7F800000);
    float b0a = INFF, b0b = INFF, b1a = INFF, b1b = INFF;

    #pragma unroll 4
    for (int t = 0; t < CHUNK/2; t++) {
        const ull xv = sxu[t], yv = syu[t], zv = szu[t], cv = scu[t];
        float lo, hi;
        ull a0 = fma2(xv, q0xp, fma2(yv, q0yp, fma2(zv, q0zp, cv)));
        unpk(a0, lo, hi); b0a = fminf(b0a, lo); b0b = fminf(b0b, hi);
        ull a1 = fma2(xv, q1xp, fma2(yv, q1yp, fma2(zv, q1zp, cv)));
        unpk(a1, lo, hi); b1a = fminf(b1a, lo); b1b = fminf(b1b, hi);
    }

    const float d0 = fmaxf(fminf(b0a, b0b) + (q0x*q0x + q0y*q0y + q0z*q0z), 0.f);
    const float d1 = fmaxf(fminf(b1a, b1b) + (q1x*q1x + q1y*q1y + q1z*q1z), 0.f);
    atomicMin(&g_minxy[b*NPTS + n0],       __float_as_uint(d0));
    atomicMin(&g_minxy[b*NPTS + n0 + BLK], __float_as_uint(d1));
}

// ref -> pred: argmin over pred (candidates = pred packed arrays), queries = ref points.
__global__ void yx_kernel(const float* __restrict__ ref_pts) {
    __shared__ __align__(16) float sx[CHUNK], sy[CHUNK], sz[CHUNK], sc[CHUNK];
    const int b  = blockIdx.z;
    const int c0 = blockIdx.y * CHUNK;
    const int m0 = blockIdx.x * (BLK * QPT) + threadIdx.x;
    const int base = b * NPTS + c0;

    ((float2*)sx)[threadIdx.x] = ((const float2*)(g_px + base))[threadIdx.x];
    ((float2*)sy)[threadIdx.x] = ((const float2*)(g_py + base))[threadIdx.x];
    ((float2*)sz)[threadIdx.x] = ((const float2*)(g_pz + base))[threadIdx.x];
    ((float2*)sc)[threadIdx.x] = ((const float2*)(g_pc + base))[threadIdx.x];

    const float* q0p = ref_pts + (size_t)(b*NPTS + m0) * 3;
    const float* q1p = ref_pts + (size_t)(b*NPTS + m0 + BLK) * 3;
    const float q0x = q0p[0], q0y = q0p[1], q0z = q0p[2];
    const float q1x = q1p[0], q1y = q1p[1], q1z = q1p[2];
    const ull q0xp = pk2(q0x), q0yp = pk2(q0y), q0zp = pk2(q0z);
    const ull q1xp = pk2(q1x), q1yp = pk2(q1y), q1zp = pk2(q1z);
    __syncthreads();

    const ull* sxu = (const ull*)sx; const ull* syu = (const ull*)sy;
    const ull* szu = (const ull*)sz; const ull* scu = (const ull*)sc;

    const float INFF = __int_as_float(0x7F800000);
    float best0 = INFF, best1 = INFF;
    int bi0 = c0, bi1 = c0;

    #pragma unroll 2
    for (int t = 0; t < CHUNK/2; t += 2) {
        const ull xv0 = sxu[t],   yv0 = syu[t],   zv0 = szu[t],   cv0 = scu[t];
        const ull xv1 = sxu[t+1], yv1 = syu[t+1], zv1 = szu[t+1], cv1 = scu[t+1];
        const int cb = c0 + 2*t;
        float v0, v1, v2, v3;
        {
            ull a0 = fma2(xv0, q0xp, fma2(yv0, q0yp, fma2(zv0, q0zp, cv0)));
            ull a1 = fma2(xv1, q0xp, fma2(yv1, q0yp, fma2(zv1, q0zp, cv1)));
            unpk(a0, v0, v1); unpk(a1, v2, v3);
            float mg = fminf(fminf(v0, v1), fminf(v2, v3));
            if (mg < best0) {   // rare path: ~9 improvements per 8192 candidates
                if (v0 < best0) { best0 = v0; bi0 = cb; }
                if (v1 < best0) { best0 = v1; bi0 = cb + 1; }
                if (v2 < best0) { best0 = v2; bi0 = cb + 2; }
                if (v3 < best0) { best0 = v3; bi0 = cb + 3; }
            }
        }
        {
            ull a0 = fma2(xv0, q1xp, fma2(yv0, q1yp, fma2(zv0, q1zp, cv0)));
            ull a1 = fma2(xv1, q1xp, fma2(yv1, q1yp, fma2(zv1, q1zp, cv1)));
            unpk(a0, v0, v1); unpk(a1, v2, v3);
            float mg = fminf(fminf(v0, v1), fminf(v2, v3));
            if (mg < best1) {
                if (v0 < best1) { best1 = v0; bi1 = cb; }
                if (v1 < best1) { best1 = v1; bi1 = cb + 1; }
                if (v2 < best1) { best1 = v2; bi1 = cb + 2; }
                if (v3 < best1) { best1 = v3; bi1 = cb + 3; }
            }
        }
    }

    atomicMin(&g_closest[b*NPTS + m0],
              ((ull)fkey(best0) << 32) | (unsigned)bi0);
    atomicMin(&g_closest[b*NPTS + m0 + BLK],
              ((ull)fkey(best1) << 32) | (unsigned)bi1);
}

// Parallel deterministic finalization: 64 blocks x 256 threads = exactly BB*NPTS elems.
__global__ void final_partial(const float* __restrict__ pred_sdfs,
                              const float* __restrict__ pred_cols,
                              const float* __restrict__ ref_sdfs,
                              const float* __restrict__ ref_cols) {
    const int i = blockIdx.x * BLK + threadIdx.x;   // i in [0, BB*NPTS)
    const int b = i >> 13;

    const ull p = g_closest[i];
    const unsigned idx = (unsigned)(p & 0xFFFFFFFFu);
    const float val = funkey((unsigned)(p >> 32));
    const float d_yx = fmaxf(val + g_rc[i], 0.f);

    const float* pc = pred_cols + (size_t)i * 3;
    const float* rc = ref_cols + ((size_t)(b << 13) + idx) * 3;
    double vals[4];
    vals[0] = fabsf(ref_sdfs[(b << 13) + idx] - pred_sdfs[i]);
    vals[1] = (double)(fabsf(rc[0]-pc[0]) + fabsf(rc[1]-pc[1]) + fabsf(rc[2]-pc[2]));
    vals[2] = d_yx;
    vals[3] = __uint_as_float(g_minxy[i]);

    __shared__ double red[BLK];
    for (int k = 0; k < 4; k++) {
        red[threadIdx.x] = vals[k];
        __syncthreads();
        for (int s = BLK/2; s > 0; s >>= 1) {
            if (threadIdx.x < s) red[threadIdx.x] += red[threadIdx.x + s];
            __syncthreads();
        }
        if (threadIdx.x == 0) g_part[blockIdx.x * 4 + k] = red[0];
        __syncthreads();
    }
}

__global__ void combine_kernel(float* __restrict__ out) {
    __shared__ double red[PBLK];
    const int t = threadIdx.x;   // 64 threads
    double tot[4];
    for (int k = 0; k < 4; k++) {
        red[t] = g_part[t * 4 + k];
        __syncthreads();
        for (int s = PBLK/2; s > 0; s >>= 1) {
            if (t < s) red[t] += red[t + s];
            __syncthreads();
        }
        tot[k] = red[0];
        __syncthreads();
    }
    if (t == 0) {
        out[0] = (float)(tot[0] / (double)(BB * NPTS));
        out[1] = (float)(tot[1] / (double)(BB * NPTS * 3));
        out[2] = (float)(tot[3] / (double)(BB * NPTS) + tot[2] / (double)(BB * NPTS));
    }
}

extern "C" void kernel_launch(void* const* d_in, const int* in_sizes, int n_in,
                              void* d_out, int out_size) {
    const float* pred_pts  = (const float*)d_in[0];
    const float* pred_sdfs = (const float*)d_in[1];
    const float* pred_cols = (const float*)d_in[2];
    const float* ref_pts   = (const float*)d_in[3];
    const float* ref_sdfs  = (const float*)d_in[4];
    const float* ref_cols  = (const float*)d_in[5];
    float* out = (float*)d_out;

    prep_kernel<<<(BB*NPTS + 255) / 256, 256>>>(pred_pts, ref_pts);
    yx_kernel<<<dim3(GX, NSPLIT, BB), BLK>>>(ref_pts);
    xy_kernel<<<dim3(GX, NSPLIT, BB), BLK>>>(pred_pts);
    final_partial<<<PBLK, BLK>>>(pred_sdfs, pred_cols, ref_sdfs, ref_cols);
    combine_kernel<<<1, PBLK>>>(out);
}

// round 4
// speedup vs baseline: 1.9925x; 1.0163x over previous
#include <cuda_runtime.h>
#include <cstdint>

#define BB 2
#define NPTS 8192
#define BLK 256
#define QPT 2
#define NSPLIT 16
#define CHUNK (NPTS / NSPLIT)     // 512 candidates per block
#define GX (NPTS / (BLK * QPT))   // 16
#define FBLKS 128
#define FBLK_T 128

typedef unsigned long long ull;

// Scratch (device globals; no allocations allowed)
__device__ float g_px[BB*NPTS], g_py[BB*NPTS], g_pz[BB*NPTS], g_pc[BB*NPTS]; // pred: -2x,-2y,-2z,|p|^2
__device__ float g_rx[BB*NPTS], g_ry[BB*NPTS], g_rz[BB*NPTS], g_rc[BB*NPTS]; // ref:  -2x,-2y,-2z,|r|^2
__device__ ull      g_closest[BB*NPTS];   // packed (key(val)<<32)|pred_idx per ref point
__device__ unsigned g_minxy[BB*NPTS];     // key(val) per pred point
__device__ double   g_part[FBLKS*4];
__device__ unsigned g_ctr;

__device__ __forceinline__ ull fma2(ull a, ull b, ull c){
    ull d; asm("fma.rn.f32x2 %0, %1, %2, %3;" : "=l"(d) : "l"(a), "l"(b), "l"(c)); return d;
}
__device__ __forceinline__ ull pk2(float x){
    ull v; asm("mov.b64 %0, {%1, %2};" : "=l"(v)
               : "r"(__float_as_uint(x)), "r"(__float_as_uint(x)));
    return v;
}
__device__ __forceinline__ void unpk(ull v, float& lo, float& hi){
    unsigned a, b;
    asm("mov.b64 {%0, %1}, %2;" : "=r"(a), "=r"(b) : "l"(v));
    lo = __uint_as_float(a); hi = __uint_as_float(b);
}
// Monotone float->uint key (handles negatives), invertible.
__device__ __forceinline__ unsigned fkey(float f){
    unsigned b = __float_as_uint(f);
    return b ^ ((unsigned)((int)b >> 31) | 0x80000000u);
}
__device__ __forceinline__ float funkey(unsigned u){
    unsigned b = u ^ ((u & 0x80000000u) ? 0x80000000u : 0xFFFFFFFFu);
    return __uint_as_float(b);
}

__global__ void prep_kernel(const float* __restrict__ pred_pts,
                            const float* __restrict__ ref_pts) {
    int i = blockIdx.x * blockDim.x + threadIdx.x;
    if (i == 0) g_ctr = 0;
    if (i >= BB * NPTS) return;
    float x = pred_pts[3*i], y = pred_pts[3*i+1], z = pred_pts[3*i+2];
    g_px[i] = -2.f*x; g_py[i] = -2.f*y; g_pz[i] = -2.f*z;
    g_pc[i] = x*x + y*y + z*z;
    x = ref_pts[3*i]; y = ref_pts[3*i+1]; z = ref_pts[3*i+2];
    g_rx[i] = -2.f*x; g_ry[i] = -2.f*y; g_rz[i] = -2.f*z;
    g_rc[i] = x*x + y*y + z*z;
    g_closest[i] = 0xFFFFFFFFFFFFFFFFull;
    g_minxy[i]   = 0xFFFFFFFFu;
}

// Fused distance kernel. blockIdx.y < NSPLIT: xy role (queries=pred, candidates=ref, plain min).
// blockIdx.y >= NSPLIT: yx role (queries=ref, candidates=pred, argmin).
// Score val = -2 q.c + |c|^2 = d2 - |q|^2 (same ordering as d2 for fixed query).
__global__ void __launch_bounds__(BLK) dist_kernel(const float* __restrict__ pred_pts,
                                                   const float* __restrict__ ref_pts) {
    __shared__ __align__(16) float sx[CHUNK], sy[CHUNK], sz[CHUNK], sc[CHUNK];
    const int b   = blockIdx.z;
    const bool yx = (blockIdx.y >= NSPLIT);
    const int cy  = yx ? (blockIdx.y - NSPLIT) : blockIdx.y;
    const int c0  = cy * CHUNK;
    const int q0  = blockIdx.x * (BLK * QPT) + threadIdx.x;
    const int base = b * NPTS + c0;

    const float* cx = yx ? g_px : g_rx;
    const float* cyy = yx ? g_py : g_ry;
    const float* cz = yx ? g_pz : g_rz;
    const float* cc = yx ? g_pc : g_rc;
    ((float2*)sx)[threadIdx.x] = ((const float2*)(cx  + base))[threadIdx.x];
    ((float2*)sy)[threadIdx.x] = ((const float2*)(cyy + base))[threadIdx.x];
    ((float2*)sz)[threadIdx.x] = ((const float2*)(cz  + base))[threadIdx.x];
    ((float2*)sc)[threadIdx.x] = ((const float2*)(cc  + base))[threadIdx.x];

    const float* qsrc = yx ? ref_pts : pred_pts;
    const float* q0p = qsrc + (size_t)(b*NPTS + q0) * 3;
    const float* q1p = qsrc + (size_t)(b*NPTS + q0 + BLK) * 3;
    const ull q0xp = pk2(q0p[0]), q0yp = pk2(q0p[1]), q0zp = pk2(q0p[2]);
    const ull q1xp = pk2(q1p[0]), q1yp = pk2(q1p[1]), q1zp = pk2(q1p[2]);
    __syncthreads();

    const ulonglong2* x2p = (const ulonglong2*)sx;
    const ulonglong2* y2p = (const ulonglong2*)sy;
    const ulonglong2* z2p = (const ulonglong2*)sz;
    const ulonglong2* c2p = (const ulonglong2*)sc;

    const float INFF = __int_as_float(0x7F800000);

    if (!yx) {
        float b0a = INFF, b0b = INFF, b1a = INFF, b1b = INFF;
        #pragma unroll 4
        for (int t = 0; t < CHUNK/4; t++) {
            const ulonglong2 xv = x2p[t], yv = y2p[t], zv = z2p[t], cv = c2p[t];
            float lo, hi;
            ull a;
            a = fma2(xv.x, q0xp, fma2(yv.x, q0yp, fma2(zv.x, q0zp, cv.x)));
            unpk(a, lo, hi); b0a = fminf(b0a, lo); b0b = fminf(b0b, hi);
            a = fma2(xv.y, q0xp, fma2(yv.y, q0yp, fma2(zv.y, q0zp, cv.y)));
            unpk(a, lo, hi); b0a = fminf(b0a, lo); b0b = fminf(b0b, hi);
            a = fma2(xv.x, q1xp, fma2(yv.x, q1yp, fma2(zv.x, q1zp, cv.x)));
            unpk(a, lo, hi); b1a = fminf(b1a, lo); b1b = fminf(b1b, hi);
            a = fma2(xv.y, q1xp, fma2(yv.y, q1yp, fma2(zv.y, q1zp, cv.y)));
            unpk(a, lo, hi); b1a = fminf(b1a, lo); b1b = fminf(b1b, hi);
        }
        atomicMin(&g_minxy[b*NPTS + q0],       fkey(fminf(b0a, b0b)));
        atomicMin(&g_minxy[b*NPTS + q0 + BLK], fkey(fminf(b1a, b1b)));
    } else {
        float best0 = INFF, best1 = INFF;
        int bi0 = c0, bi1 = c0;
        #pragma unroll 2
        for (int t = 0; t < CHUNK/4; t++) {
            const ulonglong2 xv = x2p[t], yv = y2p[t], zv = z2p[t], cv = c2p[t];
            ull a0 = fma2(xv.x, q0xp, fma2(yv.x, q0yp, fma2(zv.x, q0zp, cv.x)));
            ull a1 = fma2(xv.y, q0xp, fma2(yv.y, q0yp, fma2(zv.y, q0zp, cv.y)));
            ull a2 = fma2(xv.x, q1xp, fma2(yv.x, q1yp, fma2(zv.x, q1zp, cv.x)));
            ull a3 = fma2(xv.y, q1xp, fma2(yv.y, q1yp, fma2(zv.y, q1zp, cv.y)));
            float v0, v1, v2, v3, w0, w1, w2, w3;
            unpk(a0, v0, v1); unpk(a1, v2, v3);
            unpk(a2, w0, w1); unpk(a3, w2, w3);
            const float mg0 = fminf(fminf(v0, v1), fminf(v2, v3));
            const float mg1 = fminf(fminf(w0, w1), fminf(w2, w3));
            if (mg0 < best0 || mg1 < best1) {  // rarely taken (~9 hits / 8192 cands)
                const int cb = c0 + 4*t;
                if (v0 < best0) { best0 = v0; bi0 = cb; }
                if (v1 < best0) { best0 = v1; bi0 = cb + 1; }
                if (v2 < best0) { best0 = v2; bi0 = cb + 2; }
                if (v3 < best0) { best0 = v3; bi0 = cb + 3; }
                if (w0 < best1) { best1 = w0; bi1 = cb; }
                if (w1 < best1) { best1 = w1; bi1 = cb + 1; }
                if (w2 < best1) { best1 = w2; bi1 = cb + 2; }
                if (w3 < best1) { best1 = w3; bi1 = cb + 3; }
            }
        }
        atomicMin(&g_closest[b*NPTS + q0],
                  ((ull)fkey(best0) << 32) | (unsigned)bi0);
        atomicMin(&g_closest[b*NPTS + q0 + BLK],
                  ((ull)fkey(best1) << 32) | (unsigned)bi1);
    }
}

// Finalization: per-element losses, warp-shuffle reduce, last-block combines (deterministic
// fixed-order trees; ticket only selects WHO combines, not the order of sums).
__global__ void __launch_bounds__(FBLK_T) final_kernel(const float* __restrict__ pred_sdfs,
                                                       const float* __restrict__ pred_cols,
                                                       const float* __restrict__ ref_sdfs,
                                                       const float* __restrict__ ref_cols,
                                                       float* __restrict__ out) {
    const int i = blockIdx.x * FBLK_T + threadIdx.x;   // [0, BB*NPTS)
    const int b = i >> 13;
    const int lane = threadIdx.x & 31;
    const int wid = threadIdx.x >> 5;

    const ull p = g_closest[i];
    const unsigned idx = (unsigned)(p & 0xFFFFFFFFu);
    const float d_yx = fmaxf(funkey((unsigned)(p >> 32)) + g_rc[i], 0.f);
    const float d_xy = fmaxf(funkey(g_minxy[i]) + g_pc[i], 0.f);

    const float* pc = pred_cols + (size_t)i * 3;
    const float* rc = ref_cols + ((size_t)(b << 13) + idx) * 3;
    double vals[4];
    vals[0] = fabsf(ref_sdfs[(b << 13) + idx] - pred_sdfs[i]);
    vals[1] = (double)(fabsf(rc[0]-pc[0]) + fabsf(rc[1]-pc[1]) + fabsf(rc[2]-pc[2]));
    vals[2] = d_yx;
    vals[3] = d_xy;

    __shared__ double sred[4][4];   // [warp][k]
    #pragma unroll
    for (int k = 0; k < 4; k++) {
        double v = vals[k];
        #pragma unroll
        for (int s = 16; s > 0; s >>= 1) v += __shfl_down_sync(0xFFFFFFFFu, v, s);
        if (lane == 0) sred[wid][k] = v;
    }
    __syncthreads();
    if (threadIdx.x == 0) {
        #pragma unroll
        for (int k = 0; k < 4; k++)
            g_part[blockIdx.x * 4 + k] = sred[0][k] + sred[1][k] + sred[2][k] + sred[3][k];
    }

    __threadfence();
    __shared__ unsigned ticket;
    if (threadIdx.x == 0) ticket = atomicAdd(&g_ctr, 1u);
    __syncthreads();
    if (ticket != FBLKS - 1) return;

    __threadfence();
    volatile double* vp = (volatile double*)g_part;
    double tv[4];
    #pragma unroll
    for (int k = 0; k < 4; k++) tv[k] = vp[threadIdx.x * 4 + k];  // thread t = block t's partial
    #pragma unroll
    for (int k = 0; k < 4; k++) {
        double v = tv[k];
        #pragma unroll
        for (int s = 16; s > 0; s >>= 1) v += __shfl_down_sync(0xFFFFFFFFu, v, s);
        if (lane == 0) sred[wid][k] = v;
    }
    __syncthreads();
    if (threadIdx.x == 0) {
        double t0 = sred[0][0] + sred[1][0] + sred[2][0] + sred[3][0];
        double t1 = sred[0][1] + sred[1][1] + sred[2][1] + sred[3][1];
        double t2 = sred[0][2] + sred[1][2] + sred[2][2] + sred[3][2];
        double t3 = sred[0][3] + sred[1][3] + sred[2][3] + sred[3][3];
        out[0] = (float)(t0 / (double)(BB * NPTS));
        out[1] = (float)(t1 / (double)(BB * NPTS * 3));
        out[2] = (float)(t3 / (double)(BB * NPTS) + t2 / (double)(BB * NPTS));
    }
}

extern "C" void kernel_launch(void* const* d_in, const int* in_sizes, int n_in,
                              void* d_out, int out_size) {
    const float* pred_pts  = (const float*)d_in[0];
    const float* pred_sdfs = (const float*)d_in[1];
    const float* pred_cols = (const float*)d_in[2];
    const float* ref_pts   = (const float*)d_in[3];
    const float* ref_sdfs  = (const float*)d_in[4];
    const float* ref_cols  = (const float*)d_in[5];
    float* out = (float*)d_out;

    prep_kernel<<<(BB*NPTS + 255) / 256, 256>>>(pred_pts, ref_pts);
    dist_kernel<<<dim3(GX, 2*NSPLIT, BB), BLK>>>(pred_pts, ref_pts);
    final_kernel<<<FBLKS, FBLK_T>>>(pred_sdfs, pred_cols, ref_sdfs, ref_cols, out);
}